// round 5
// baseline (speedup 1.0000x reference)
#include <cuda_runtime.h>

// x:   [B=2, 1, D=64, H=256, W=256] fp32
// out: [B=2, 16, D=64, H=256, W=256] fp32
//   even channel -> per-slice 2D sobel magnitude, odd channel -> x
//
// One warp = TWO consecutive rows (hp, hp+1) of one slice. Lane l owns two
// float4 chunks per row (w=4l and w=4l+128). 4 input rows loaded (hp-1..hp+2),
// middle rows shared between the two sobel rows. All halos via warp shuffle.
// 64 fully-coalesced streaming STG.128 per thread (2KB/channel/warp bursts).

#define W 256
#define H 256
#define DD 64
#define NB 2

__device__ __forceinline__ float fsqrt_approx(float a) {
    float r;
    asm("sqrt.approx.f32 %0, %1;" : "=f"(r) : "f"(a));
    return r;
}

__device__ __forceinline__ float4 sobel4(
    float tl, const float4& T, float tr,
    float ml, const float4& M, float mr,
    float bl, const float4& Bv, float br)
{
    float Ta[6] = { tl, T.x, T.y, T.z, T.w, tr };
    float Ma[6] = { ml, M.x, M.y, M.z, M.w, mr };
    float Ba[6] = { bl, Bv.x, Bv.y, Bv.z, Bv.w, br };
    float4 s;
    float* sp = reinterpret_cast<float*>(&s);
#pragma unroll
    for (int i = 0; i < 4; i++) {
        float gx = (Ta[i+2] - Ta[i]) + 2.f*(Ma[i+2] - Ma[i]) + (Ba[i+2] - Ba[i]);
        float gy = (Ba[i] - Ta[i]) + 2.f*(Ba[i+1] - Ta[i+1]) + (Ba[i+2] - Ta[i+2]);
        sp[i] = fsqrt_approx(gx*gx + gy*gy);
    }
    return s;
}

__global__ __launch_bounds__(256) void sobel_cat_kernel(
    const float* __restrict__ x, float* __restrict__ out)
{
    const int warp = blockIdx.x * (blockDim.x >> 5) + (threadIdx.x >> 5);
    const int lane = threadIdx.x & 31;
    const int pr   = warp & (H/2 - 1);     // row-pair index within slice
    const int hp   = pr << 1;              // first of the two rows
    const int bd   = warp >> 7;            // b*D + d
    const int w0   = lane << 2;

    const float* base = x + ((size_t)bd * H + hp) * W + w0;

    float4 z = make_float4(0.f, 0.f, 0.f, 0.f);
    // rows: a = hp-1, b = hp, c = hp+1, d = hp+2 ; chunks 0 (w0) / 1 (w0+128)
    float4 a0 = z, a1 = z, d0 = z, d1 = z;
    float4 b0 = __ldg((const float4*)base);
    float4 b1 = __ldg((const float4*)(base + 128));
    float4 c0 = __ldg((const float4*)(base + W));
    float4 c1 = __ldg((const float4*)(base + 128 + W));
    if (hp > 0) {
        a0 = __ldg((const float4*)(base - W));
        a1 = __ldg((const float4*)(base + 128 - W));
    }
    if (hp < H - 2) {
        d0 = __ldg((const float4*)(base + 2 * W));
        d1 = __ldg((const float4*)(base + 128 + 2 * W));
    }

    const unsigned full = 0xFFFFFFFFu;
    // halos per row: chunk0 left/right, chunk1 left/right
    float al0, ar0, al1, ar1, bl0, br0, bl1, br1;
    float cl0, cr0, cl1, cr1, dl0, dr0, dl1, dr1;

#define HALO(v0, v1, l0, r0, l1, r1)                                   \
    {                                                                  \
        l0 = __shfl_up_sync(full, (v0).w, 1);                          \
        r0 = __shfl_down_sync(full, (v0).x, 1);                        \
        l1 = __shfl_up_sync(full, (v1).w, 1);                          \
        r1 = __shfl_down_sync(full, (v1).x, 1);                        \
        float _x0  = __shfl_sync(full, (v1).x, 0);                     \
        float _w31 = __shfl_sync(full, (v0).w, 31);                    \
        if (lane == 0)  { l0 = 0.f;  l1 = _w31; }                      \
        if (lane == 31) { r0 = _x0;  r1 = 0.f;  }                      \
    }

    HALO(a0, a1, al0, ar0, al1, ar1)
    HALO(b0, b1, bl0, br0, bl1, br1)
    HALO(c0, c1, cl0, cr0, cl1, cr1)
    HALO(d0, d1, dl0, dr0, dl1, dr1)
#undef HALO

    // sobel for row hp (T=a, M=b, B=c) and row hp+1 (T=b, M=c, B=d)
    float4 s00 = sobel4(al0, a0, ar0, bl0, b0, br0, cl0, c0, cr0);
    float4 s01 = sobel4(al1, a1, ar1, bl1, b1, br1, cl1, c1, cr1);
    float4 s10 = sobel4(bl0, b0, br0, cl0, c0, cr0, dl0, d0, dr0);
    float4 s11 = sobel4(bl1, b1, br1, cl1, c1, cr1, dl1, d1, dr1);

    const int bb = bd >> 6;           // bd / D
    const int dd = bd & (DD - 1);     // bd % D
    const size_t cs = (size_t)DD * H * W;   // channel stride (elems)
    float* obase = out + (((size_t)bb * 16 * DD + dd) * H + hp) * W + w0;

#pragma unroll
    for (int c = 0; c < 8; c++) {
        float* p = obase + (size_t)(2 * c) * cs;   // sobel channel
        __stcs((float4*)(p),           s00);
        __stcs((float4*)(p + 128),     s01);
        __stcs((float4*)(p + W),       s10);
        __stcs((float4*)(p + W + 128), s11);
        float* q = p + cs;                         // copy channel
        __stcs((float4*)(q),           b0);
        __stcs((float4*)(q + 128),     b1);
        __stcs((float4*)(q + W),       c0);
        __stcs((float4*)(q + W + 128), c1);
    }
}

extern "C" void kernel_launch(void* const* d_in, const int* in_sizes, int n_in,
                              void* d_out, int out_size)
{
    const float* x = (const float*)d_in[0];
    float* out = (float*)d_out;

    // one warp per row-pair: NB*DD*(H/2) = 16384 warps, 8 warps per block
    const int total_warps = NB * DD * (H / 2);
    const int threads = 256;
    const int blocks = total_warps * 32 / threads;   // 2048
    sobel_cat_kernel<<<blocks, threads>>>(x, out);
}